// round 5
// baseline (speedup 1.0000x reference)
#include <cuda_runtime.h>
#include <cuda_bf16.h>
#include <cstdint>

#define SEQ 2048
#define DIM 512
#define QT  64
#define KT  32
#define NT_ 512

#define QS32 260   // word stride of Q/K bf16-pair rows (260 % 32 == 4)
#define HSTR 520   // halfword stride (= 2*QS32)
#define PS32 20    // word stride of P pair rows
#define SPST 36    // float stride of partial-score rows

// smem word offsets
#define W_Q0 0
#define W_Q1 16640
#define W_K0 33280
#define W_K1 41600
#define W_SP0 49920
#define W_SP1 52224
#define W_P0 54528
#define W_P1 55808
#define W_M  57088
#define W_L  57152
#define W_SC 57216
#define SMEM_WORDS 57280
#define SMEM_BYTES (SMEM_WORDS * 4)   // 229,120 B

__device__ __forceinline__ uint32_t smem_u32(const void* p) {
    uint32_t a;
    asm("{ .reg .u64 t; cvta.to.shared.u64 t, %1; cvt.u32.u64 %0, t; }" : "=r"(a) : "l"(p));
    return a;
}

// split fp32 pair (x=even, y=odd) into bf16 hi pair + bf16 residual pair
__device__ __forceinline__ void cvt2(float x, float y, uint32_t& hip, uint32_t& lop) {
    __nv_bfloat16 bx = __float2bfloat16_rn(x);
    __nv_bfloat16 by = __float2bfloat16_rn(y);
    float rx = x - __bfloat162float(bx);
    float ry = y - __bfloat162float(by);
    __nv_bfloat162 h; h.x = bx; h.y = by;
    __nv_bfloat162 l; l.x = __float2bfloat16_rn(rx); l.y = __float2bfloat16_rn(ry);
    hip = *reinterpret_cast<uint32_t*>(&h);
    lop = *reinterpret_cast<uint32_t*>(&l);
}

__device__ __forceinline__ void mma16(float4& d,
                                      uint32_t a0, uint32_t a1, uint32_t a2, uint32_t a3,
                                      uint32_t b0, uint32_t b1) {
    asm volatile(
        "mma.sync.aligned.m16n8k16.row.col.f32.bf16.bf16.f32 "
        "{%0,%1,%2,%3},{%4,%5,%6,%7},{%8,%9},{%0,%1,%2,%3};"
        : "+f"(d.x), "+f"(d.y), "+f"(d.z), "+f"(d.w)
        : "r"(a0), "r"(a1), "r"(a2), "r"(a3), "r"(b0), "r"(b1));
}

__device__ __forceinline__ void ldsm4(uint32_t& r0, uint32_t& r1, uint32_t& r2, uint32_t& r3,
                                      uint32_t a) {
    asm volatile("ldmatrix.sync.aligned.m8n8.x4.shared.b16 {%0,%1,%2,%3}, [%4];"
                 : "=r"(r0), "=r"(r1), "=r"(r2), "=r"(r3) : "r"(a));
}
__device__ __forceinline__ void ldsm2(uint32_t& r0, uint32_t& r1, uint32_t a) {
    asm volatile("ldmatrix.sync.aligned.m8n8.x2.shared.b16 {%0,%1}, [%2];"
                 : "=r"(r0), "=r"(r1) : "r"(a));
}
__device__ __forceinline__ void ldsm2t(uint32_t& r0, uint32_t& r1, uint32_t a) {
    asm volatile("ldmatrix.sync.aligned.m8n8.x2.trans.shared.b16 {%0,%1}, [%2];"
                 : "=r"(r0), "=r"(r1) : "r"(a));
}

__global__ void __launch_bounds__(NT_, 1)
attn_flash_v5(const float* __restrict__ enc,
              const float* __restrict__ dec,
              float* __restrict__ out) {
    extern __shared__ uint32_t sm[];
    float* fSp0 = (float*)(sm + W_SP0);
    float* fSp1 = (float*)(sm + W_SP1);
    float* fM   = (float*)(sm + W_M);
    float* fL   = (float*)(sm + W_L);
    float* fSc  = (float*)(sm + W_SC);

    const uint32_t sb = smem_u32(sm);
    const int tid  = threadIdx.x;
    const int lane = tid & 31;
    const int wid  = tid >> 5;
    const int g = lane >> 2;
    const int t = lane & 3;
    const int l16 = lane & 15;
    const int lhi = lane >> 4;
    const int l8  = lane & 7;
    const int lm2 = (lane >> 3) & 1;

    const int b  = blockIdx.x >> 5;
    const int q0 = (blockIdx.x & 31) * QT;
    const float* decb = dec + ((size_t)b * SEQ + q0) * DIM;
    const float* encb = enc + (size_t)b * SEQ * DIM;

    // ---- load Q tile, split to bf16 hi/lo ----
#pragma unroll
    for (int j = 0; j < 16; j++) {
        int i  = tid + j * NT_;
        int r  = i >> 7;
        int c4 = (i & 127) << 2;
        float4 v = *(const float4*)(decb + r * DIM + c4);
        uint32_t h0, l0, h1, l1;
        cvt2(v.x, v.y, h0, l0);
        cvt2(v.z, v.w, h1, l1);
        uint32_t w = r * QS32 + (c4 >> 1);
        *(uint2*)(sm + W_Q0 + w) = make_uint2(h0, h1);
        *(uint2*)(sm + W_Q1 + w) = make_uint2(l0, l1);
    }
    if (tid < QT) { fM[tid] = -1e30f; fL[tid] = 0.0f; }

    // GEMM1 roles: 4m x 2n x 2k
    const int wm = wid >> 2;
    const int wn = (wid >> 1) & 1;
    const int wk = wid & 1;
    const int nb = wid * 32;       // GEMM2 column slice

    // ---- prefetch K[0] into registers ----
    float4 kreg[8];
#pragma unroll
    for (int j = 0; j < 8; j++) {
        int i = tid + j * NT_;
        int r = i >> 7, c4 = (i & 127) << 2;
        kreg[j] = *(const float4*)(encb + (size_t)r * DIM + c4);
    }

    // ldmatrix byte-address bases
    uint32_t aQ0 = sb + 4u * (W_Q0 + (wm * 16 + l16) * QS32) + wk * 512 + lhi * 16;
    uint32_t aQ1 = aQ0 + 4u * (W_Q1 - W_Q0);
    uint32_t aB0[2], aB1[2];
#pragma unroll
    for (int nt = 0; nt < 2; nt++) {
        int n = wn * 16 + nt * 8 + l8;
        aB0[nt] = sb + 4u * (W_K0 + n * QS32) + wk * 512 + lm2 * 16;
        aB1[nt] = aB0[nt] + 4u * (W_K1 - W_K0);
    }
    uint32_t aP0 = sb + 4u * (W_P0 + l16 * PS32) + lhi * 16;
    uint32_t aP1 = aP0 + 4u * (W_P1 - W_P0);
    uint32_t aE0 = sb + 4u * (W_K0 + l16 * QS32) + nb * 2;
    uint32_t aE1 = aE0 + 4u * (W_K1 - W_K0);

    float4 o[4][4];
#pragma unroll
    for (int mt = 0; mt < 4; mt++)
#pragma unroll
        for (int nt = 0; nt < 4; nt++) o[mt][nt] = make_float4(0.f, 0.f, 0.f, 0.f);

    for (int kt = 0; kt < SEQ / KT; kt++) {
        __syncthreads();   // prior GEMM2 done with K/P; Sp free

        // ---- store K tile from prefetch regs, split hi/lo ----
#pragma unroll
        for (int j = 0; j < 8; j++) {
            int i = tid + j * NT_;
            int r = i >> 7, c4 = (i & 127) << 2;
            uint32_t h0, l0, h1, l1;
            cvt2(kreg[j].x, kreg[j].y, h0, l0);
            cvt2(kreg[j].z, kreg[j].w, h1, l1);
            uint32_t w = r * QS32 + (c4 >> 1);
            *(uint2*)(sm + W_K0 + w) = make_uint2(h0, h1);
            *(uint2*)(sm + W_K1 + w) = make_uint2(l0, l1);
        }
        // ---- prefetch next K tile (overlaps GEMM1+softmax+GEMM2) ----
        if (kt + 1 < SEQ / KT) {
            const float* kg = encb + (size_t)(kt + 1) * KT * DIM;
#pragma unroll
            for (int j = 0; j < 8; j++) {
                int i = tid + j * NT_;
                int r = i >> 7, c4 = (i & 127) << 2;
                kreg[j] = *(const float4*)(kg + (size_t)r * DIM + c4);
            }
        }
        __syncthreads();

        // ---- GEMM1 (split-k): partial S[16x16] per warp over its 256-elem k-slice ----
        {
            float4 c0 = make_float4(0.f, 0.f, 0.f, 0.f), c1 = c0;
#pragma unroll
            for (int s = 0; s < 16; s++) {
                uint32_t ah0, ah1, ah2, ah3, al0, al1, al2, al3;
                ldsm4(ah0, ah1, ah2, ah3, aQ0 + s * 32);
                ldsm4(al0, al1, al2, al3, aQ1 + s * 32);
                uint32_t bh0, bh1, bl0, bl1;
                ldsm2(bh0, bh1, aB0[0] + s * 32);
                ldsm2(bl0, bl1, aB1[0] + s * 32);
                mma16(c0, ah0, ah1, ah2, ah3, bl0, bl1);
                mma16(c0, al0, al1, al2, al3, bh0, bh1);
                mma16(c0, ah0, ah1, ah2, ah3, bh0, bh1);
                ldsm2(bh0, bh1, aB0[1] + s * 32);
                ldsm2(bl0, bl1, aB1[1] + s * 32);
                mma16(c1, ah0, ah1, ah2, ah3, bl0, bl1);
                mma16(c1, al0, al1, al2, al3, bh0, bh1);
                mma16(c1, ah0, ah1, ah2, ah3, bh0, bh1);
            }
            float* sp = wk ? fSp1 : fSp0;
            int rr = wm * 16 + g;
            int cc = wn * 16 + (t << 1);
            *(float2*)(sp + rr * SPST + cc)           = make_float2(c0.x, c0.y);
            *(float2*)(sp + (rr + 8) * SPST + cc)     = make_float2(c0.z, c0.w);
            *(float2*)(sp + rr * SPST + cc + 8)       = make_float2(c1.x, c1.y);
            *(float2*)(sp + (rr + 8) * SPST + cc + 8) = make_float2(c1.z, c1.w);
        }
        __syncthreads();

        // ---- online softmax (sum the 2 k-partials, then as before) ----
        {
            int row = (wid << 2) + (lane >> 3);
            int cb  = (lane & 7) << 2;
            float4 u = *(float4*)(fSp0 + row * SPST + cb);
            float4 v = *(float4*)(fSp1 + row * SPST + cb);
            float s0 = u.x + v.x, s1 = u.y + v.y, s2 = u.z + v.z, s3 = u.w + v.w;
            float mx = fmaxf(fmaxf(s0, s1), fmaxf(s2, s3));
            mx = fmaxf(mx, __shfl_xor_sync(0xffffffffu, mx, 1));
            mx = fmaxf(mx, __shfl_xor_sync(0xffffffffu, mx, 2));
            mx = fmaxf(mx, __shfl_xor_sync(0xffffffffu, mx, 4));
            float mo = fM[row];
            float mn = fmaxf(mo, mx);
            float p0 = __expf(s0 - mn), p1 = __expf(s1 - mn);
            float p2 = __expf(s2 - mn), p3 = __expf(s3 - mn);
            float su = p0 + p1 + p2 + p3;
            su += __shfl_xor_sync(0xffffffffu, su, 1);
            su += __shfl_xor_sync(0xffffffffu, su, 2);
            su += __shfl_xor_sync(0xffffffffu, su, 4);
            if ((lane & 7) == 0) {
                float sc = __expf(mo - mn);
                fSc[row] = sc;
                fM[row]  = mn;
                fL[row]  = fL[row] * sc + su;
            }
            uint32_t h0, l0, h1, l1;
            cvt2(p0, p1, h0, l0);
            cvt2(p2, p3, h1, l1);
            uint32_t w = row * PS32 + ((lane & 7) << 1);
            *(uint2*)(sm + W_P0 + w) = make_uint2(h0, h1);
            *(uint2*)(sm + W_P1 + w) = make_uint2(l0, l1);
        }
        __syncthreads();

        // ---- rescale O ----
        {
            float sc[8];
#pragma unroll
            for (int j = 0; j < 8; j++) sc[j] = fSc[g + 8 * j];
#pragma unroll
            for (int mt = 0; mt < 4; mt++) {
                float slo = sc[2 * mt], shi = sc[2 * mt + 1];
#pragma unroll
                for (int nt = 0; nt < 4; nt++) {
                    o[mt][nt].x *= slo; o[mt][nt].y *= slo;
                    o[mt][nt].z *= shi; o[mt][nt].w *= shi;
                }
            }
        }

        // ---- GEMM2: O[64 x 32/warp] += P @ E (ldmatrix operands) ----
#pragma unroll
        for (int ks = 0; ks < 2; ks++) {
            uint32_t A0[4][4], A1[4][4];
#pragma unroll
            for (int mt = 0; mt < 4; mt++) {
                uint32_t off = (uint32_t)(mt * 16 * PS32 + ks * 8) * 4;
                ldsm4(A0[mt][0], A0[mt][1], A0[mt][2], A0[mt][3], aP0 + off);
                ldsm4(A1[mt][0], A1[mt][1], A1[mt][2], A1[mt][3], aP1 + off);
            }
#pragma unroll
            for (int nt = 0; nt < 4; nt++) {
                uint32_t off = (uint32_t)(ks * 16 * QS32) * 4 + nt * 16;
                uint32_t B00, B01, B10, B11;
                ldsm2t(B00, B01, aE0 + off);
                ldsm2t(B10, B11, aE1 + off);
#pragma unroll
                for (int mt = 0; mt < 4; mt++) {
                    mma16(o[mt][nt], A0[mt][0], A0[mt][1], A0[mt][2], A0[mt][3], B10, B11);
                    mma16(o[mt][nt], A1[mt][0], A1[mt][1], A1[mt][2], A1[mt][3], B00, B01);
                    mma16(o[mt][nt], A0[mt][0], A0[mt][1], A0[mt][2], A0[mt][3], B00, B01);
                }
            }
        }
    }

    __syncthreads();

    // ---- epilogue: normalize by 1/l and store ----
    {
        float il[8];
#pragma unroll
        for (int j = 0; j < 8; j++) il[j] = 1.0f / fL[g + 8 * j];
        float* ob = out + ((size_t)b * SEQ + q0) * DIM;
#pragma unroll
        for (int mt = 0; mt < 4; mt++) {
            float ilo = il[2 * mt], ihi = il[2 * mt + 1];
            int r = mt * 16 + g;
#pragma unroll
            for (int nt = 0; nt < 4; nt++) {
                int c = nb + nt * 8 + (t << 1);
                float2 v0 = make_float2(o[mt][nt].x * ilo, o[mt][nt].y * ilo);
                float2 v1 = make_float2(o[mt][nt].z * ihi, o[mt][nt].w * ihi);
                *(float2*)(ob + r * DIM + c)       = v0;
                *(float2*)(ob + (r + 8) * DIM + c) = v1;
            }
        }
    }
}

extern "C" void kernel_launch(void* const* d_in, const int* in_sizes, int n_in,
                              void* d_out, int out_size) {
    const float* enc = (const float*)d_in[0];   // enc_outputs [8,2048,512]
    const float* dec = (const float*)d_in[1];   // dec_outputs [8,2048,512]
    float* out = (float*)d_out;                 // [8,2048,512]

    cudaFuncSetAttribute(attn_flash_v5,
                         cudaFuncAttributeMaxDynamicSharedMemorySize, SMEM_BYTES);

    dim3 grid(8 * (SEQ / QT));   // 256 CTAs
    attn_flash_v5<<<grid, NT_, SMEM_BYTES>>>(enc, dec, out);
}

// round 6
// speedup vs baseline: 1.0261x; 1.0261x over previous
#include <cuda_runtime.h>
#include <cuda_bf16.h>
#include <cstdint>

#define SEQ 2048
#define DIM 512
#define QT  64
#define KT  32
#define NT_ 512

#define QS32 260   // word stride of Q/K bf16-pair rows (260 % 32 == 4)
#define HSTR 520   // halfword stride (= 2*QS32)
#define PS32 20    // word stride of P pair rows
#define SPST 36    // float stride of partial-score rows

// smem word offsets
#define W_Q0 0
#define W_Q1 16640
#define W_K0 33280
#define W_K1 41600
#define W_SP0 49920
#define W_SP1 52224
#define W_P0 54528
#define W_P1 55808
#define W_M  57088
#define W_L  57152
#define W_SC 57216
#define SMEM_WORDS 57280
#define SMEM_BYTES (SMEM_WORDS * 4)   // 229,120 B

__device__ __forceinline__ uint32_t smem_u32(const void* p) {
    uint32_t a;
    asm("{ .reg .u64 t; cvta.to.shared.u64 t, %1; cvt.u32.u64 %0, t; }" : "=r"(a) : "l"(p));
    return a;
}

// split fp32 pair (x=even, y=odd) into bf16 hi pair + bf16 residual pair
__device__ __forceinline__ void cvt2(float x, float y, uint32_t& hip, uint32_t& lop) {
    __nv_bfloat16 bx = __float2bfloat16_rn(x);
    __nv_bfloat16 by = __float2bfloat16_rn(y);
    float rx = x - __bfloat162float(bx);
    float ry = y - __bfloat162float(by);
    __nv_bfloat162 h; h.x = bx; h.y = by;
    __nv_bfloat162 l; l.x = __float2bfloat16_rn(rx); l.y = __float2bfloat16_rn(ry);
    hip = *reinterpret_cast<uint32_t*>(&h);
    lop = *reinterpret_cast<uint32_t*>(&l);
}

__device__ __forceinline__ void mma16(float4& d,
                                      uint32_t a0, uint32_t a1, uint32_t a2, uint32_t a3,
                                      uint32_t b0, uint32_t b1) {
    asm volatile(
        "mma.sync.aligned.m16n8k16.row.col.f32.bf16.bf16.f32 "
        "{%0,%1,%2,%3},{%4,%5,%6,%7},{%8,%9},{%0,%1,%2,%3};"
        : "+f"(d.x), "+f"(d.y), "+f"(d.z), "+f"(d.w)
        : "r"(a0), "r"(a1), "r"(a2), "r"(a3), "r"(b0), "r"(b1));
}

__device__ __forceinline__ void ldsm4(uint32_t& r0, uint32_t& r1, uint32_t& r2, uint32_t& r3,
                                      uint32_t a) {
    asm volatile("ldmatrix.sync.aligned.m8n8.x4.shared.b16 {%0,%1,%2,%3}, [%4];"
                 : "=r"(r0), "=r"(r1), "=r"(r2), "=r"(r3) : "r"(a));
}
__device__ __forceinline__ void ldsm2t(uint32_t& r0, uint32_t& r1, uint32_t a) {
    asm volatile("ldmatrix.sync.aligned.m8n8.x2.trans.shared.b16 {%0,%1}, [%2];"
                 : "=r"(r0), "=r"(r1) : "r"(a));
}

__global__ void __launch_bounds__(NT_, 1)
attn_flash_v6(const float* __restrict__ enc,
              const float* __restrict__ dec,
              float* __restrict__ out) {
    extern __shared__ uint32_t sm[];
    float* fSp0 = (float*)(sm + W_SP0);
    float* fSp1 = (float*)(sm + W_SP1);
    float* fM   = (float*)(sm + W_M);
    float* fL   = (float*)(sm + W_L);
    float* fSc  = (float*)(sm + W_SC);

    const uint32_t sb = smem_u32(sm);
    const int tid  = threadIdx.x;
    const int lane = tid & 31;
    const int wid  = tid >> 5;
    const int g = lane >> 2;
    const int t = lane & 3;
    const int l16 = lane & 15;
    const int lhi = lane >> 4;

    const int b  = blockIdx.x >> 5;
    const int q0 = (blockIdx.x & 31) * QT;
    const float* decb = dec + ((size_t)b * SEQ + q0) * DIM;
    const float* encb = enc + (size_t)b * SEQ * DIM;

    // ---- load Q tile, split to bf16 hi/lo ----
#pragma unroll
    for (int j = 0; j < 16; j++) {
        int i  = tid + j * NT_;
        int r  = i >> 7;
        int c4 = (i & 127) << 2;
        float4 v = *(const float4*)(decb + r * DIM + c4);
        uint32_t h0, l0, h1, l1;
        cvt2(v.x, v.y, h0, l0);
        cvt2(v.z, v.w, h1, l1);
        uint32_t w = r * QS32 + (c4 >> 1);
        *(uint2*)(sm + W_Q0 + w) = make_uint2(h0, h1);
        *(uint2*)(sm + W_Q1 + w) = make_uint2(l0, l1);
    }
    if (tid < QT) { fM[tid] = -1e30f; fL[tid] = 0.0f; }

    // GEMM1 roles: 4m x 2n x 2k
    const int wm = wid >> 2;
    const int wn = (wid >> 1) & 1;
    const int wk = wid & 1;
    const int nb = wid * 32;       // GEMM2 column slice

    // ---- prefetch K[0] into registers ----
    float4 kreg[8];
#pragma unroll
    for (int j = 0; j < 8; j++) {
        int i = tid + j * NT_;
        int r = i >> 7, c4 = (i & 127) << 2;
        kreg[j] = *(const float4*)(encb + (size_t)r * DIM + c4);
    }

    // ldmatrix byte-address bases
    uint32_t aQ0 = sb + 4u * (W_Q0 + (wm * 16 + l16) * QS32) + wk * 512 + lhi * 16;
    uint32_t aQ1 = aQ0 + 4u * (W_Q1 - W_Q0);
    // B x4: lane mi=lane>>3: matrices {nt0-klo, nt0-khi, nt1-klo, nt1-khi}
    const int mi = lane >> 3;
    const int bn = wn * 16 + (mi >> 1) * 8 + (lane & 7);
    uint32_t aBh = sb + 4u * (W_K0 + bn * QS32) + wk * 512 + (mi & 1) * 16;
    uint32_t aBl = aBh + 4u * (W_K1 - W_K0);
    uint32_t aP0 = sb + 4u * (W_P0 + l16 * PS32) + lhi * 16;
    uint32_t aP1 = aP0 + 4u * (W_P1 - W_P0);
    uint32_t aE0 = sb + 4u * (W_K0 + l16 * QS32) + nb * 2;
    uint32_t aE1 = aE0 + 4u * (W_K1 - W_K0);

    float4 o[4][4];
#pragma unroll
    for (int mt = 0; mt < 4; mt++)
#pragma unroll
        for (int nt = 0; nt < 4; nt++) o[mt][nt] = make_float4(0.f, 0.f, 0.f, 0.f);

    for (int kt = 0; kt < SEQ / KT; kt++) {
        __syncthreads();   // prior GEMM2 done with K/P; Sp free

        // ---- store K tile from prefetch regs, split hi/lo ----
#pragma unroll
        for (int j = 0; j < 8; j++) {
            int i = tid + j * NT_;
            int r = i >> 7, c4 = (i & 127) << 2;
            uint32_t h0, l0, h1, l1;
            cvt2(kreg[j].x, kreg[j].y, h0, l0);
            cvt2(kreg[j].z, kreg[j].w, h1, l1);
            uint32_t w = r * QS32 + (c4 >> 1);
            *(uint2*)(sm + W_K0 + w) = make_uint2(h0, h1);
            *(uint2*)(sm + W_K1 + w) = make_uint2(l0, l1);
        }
        // ---- prefetch next K tile (overlaps GEMM1+softmax+GEMM2) ----
        if (kt + 1 < SEQ / KT) {
            const float* kg = encb + (size_t)(kt + 1) * KT * DIM;
#pragma unroll
            for (int j = 0; j < 8; j++) {
                int i = tid + j * NT_;
                int r = i >> 7, c4 = (i & 127) << 2;
                kreg[j] = *(const float4*)(kg + (size_t)r * DIM + c4);
            }
        }
        __syncthreads();

        // ---- GEMM1 (split-k): partial S[16x16] per warp; 6 independent accumulators ----
        {
            float4 c0 = make_float4(0.f, 0.f, 0.f, 0.f);
            float4 c1 = c0, c2 = c0, c3 = c0, c4_ = c0, c5 = c0;
#pragma unroll
            for (int s = 0; s < 16; s++) {
                uint32_t ah0, ah1, ah2, ah3, al0, al1, al2, al3;
                ldsm4(ah0, ah1, ah2, ah3, aQ0 + s * 32);
                ldsm4(al0, al1, al2, al3, aQ1 + s * 32);
                uint32_t bh0, bh1, bh2, bh3, bl0, bl1, bl2, bl3;
                ldsm4(bh0, bh1, bh2, bh3, aBh + s * 32);
                ldsm4(bl0, bl1, bl2, bl3, aBl + s * 32);
                mma16(c0,  ah0, ah1, ah2, ah3, bh0, bh1);   // nt0 hi*hi
                mma16(c1,  ah0, ah1, ah2, ah3, bl0, bl1);   // nt0 hi*lo
                mma16(c2,  al0, al1, al2, al3, bh0, bh1);   // nt0 lo*hi
                mma16(c3,  ah0, ah1, ah2, ah3, bh2, bh3);   // nt1 hi*hi
                mma16(c4_, ah0, ah1, ah2, ah3, bl2, bl3);   // nt1 hi*lo
                mma16(c5,  al0, al1, al2, al3, bh2, bh3);   // nt1 lo*hi
            }
            float4 u, v;
            u.x = c0.x + c1.x + c2.x; u.y = c0.y + c1.y + c2.y;
            u.z = c0.z + c1.z + c2.z; u.w = c0.w + c1.w + c2.w;
            v.x = c3.x + c4_.x + c5.x; v.y = c3.y + c4_.y + c5.y;
            v.z = c3.z + c4_.z + c5.z; v.w = c3.w + c4_.w + c5.w;
            float* sp = wk ? fSp1 : fSp0;
            int rr = wm * 16 + g;
            int cc = wn * 16 + (t << 1);
            *(float2*)(sp + rr * SPST + cc)           = make_float2(u.x, u.y);
            *(float2*)(sp + (rr + 8) * SPST + cc)     = make_float2(u.z, u.w);
            *(float2*)(sp + rr * SPST + cc + 8)       = make_float2(v.x, v.y);
            *(float2*)(sp + (rr + 8) * SPST + cc + 8) = make_float2(v.z, v.w);
        }
        __syncthreads();

        // ---- online softmax (sum the 2 k-partials) ----
        {
            int row = (wid << 2) + (lane >> 3);
            int cb  = (lane & 7) << 2;
            float4 u = *(float4*)(fSp0 + row * SPST + cb);
            float4 v = *(float4*)(fSp1 + row * SPST + cb);
            float s0 = u.x + v.x, s1 = u.y + v.y, s2 = u.z + v.z, s3 = u.w + v.w;
            float mx = fmaxf(fmaxf(s0, s1), fmaxf(s2, s3));
            mx = fmaxf(mx, __shfl_xor_sync(0xffffffffu, mx, 1));
            mx = fmaxf(mx, __shfl_xor_sync(0xffffffffu, mx, 2));
            mx = fmaxf(mx, __shfl_xor_sync(0xffffffffu, mx, 4));
            float mo = fM[row];
            float mn = fmaxf(mo, mx);
            float p0 = __expf(s0 - mn), p1 = __expf(s1 - mn);
            float p2 = __expf(s2 - mn), p3 = __expf(s3 - mn);
            float su = p0 + p1 + p2 + p3;
            su += __shfl_xor_sync(0xffffffffu, su, 1);
            su += __shfl_xor_sync(0xffffffffu, su, 2);
            su += __shfl_xor_sync(0xffffffffu, su, 4);
            if ((lane & 7) == 0) {
                float sc = __expf(mo - mn);
                fSc[row] = sc;
                fM[row]  = mn;
                fL[row]  = fL[row] * sc + su;
            }
            uint32_t h0, l0, h1, l1;
            cvt2(p0, p1, h0, l0);
            cvt2(p2, p3, h1, l1);
            uint32_t w = row * PS32 + ((lane & 7) << 1);
            *(uint2*)(sm + W_P0 + w) = make_uint2(h0, h1);
            *(uint2*)(sm + W_P1 + w) = make_uint2(l0, l1);
        }
        __syncthreads();

        // ---- rescale O ----
        {
            float sc[8];
#pragma unroll
            for (int j = 0; j < 8; j++) sc[j] = fSc[g + 8 * j];
#pragma unroll
            for (int mt = 0; mt < 4; mt++) {
                float slo = sc[2 * mt], shi = sc[2 * mt + 1];
#pragma unroll
                for (int nt = 0; nt < 4; nt++) {
                    o[mt][nt].x *= slo; o[mt][nt].y *= slo;
                    o[mt][nt].z *= shi; o[mt][nt].w *= shi;
                }
            }
        }

        // ---- GEMM2: O[64 x 32/warp] += P @ E (ldmatrix operands) ----
#pragma unroll
        for (int ks = 0; ks < 2; ks++) {
            uint32_t A0[4][4], A1[4][4];
#pragma unroll
            for (int mt = 0; mt < 4; mt++) {
                uint32_t off = (uint32_t)(mt * 16 * PS32 + ks * 8) * 4;
                ldsm4(A0[mt][0], A0[mt][1], A0[mt][2], A0[mt][3], aP0 + off);
                ldsm4(A1[mt][0], A1[mt][1], A1[mt][2], A1[mt][3], aP1 + off);
            }
#pragma unroll
            for (int nt = 0; nt < 4; nt++) {
                uint32_t off = (uint32_t)(ks * 16 * QS32) * 4 + nt * 16;
                uint32_t B00, B01, B10, B11;
                ldsm2t(B00, B01, aE0 + off);
                ldsm2t(B10, B11, aE1 + off);
#pragma unroll
                for (int mt = 0; mt < 4; mt++) {
                    mma16(o[mt][nt], A0[mt][0], A0[mt][1], A0[mt][2], A0[mt][3], B10, B11);
                    mma16(o[mt][nt], A1[mt][0], A1[mt][1], A1[mt][2], A1[mt][3], B00, B01);
                    mma16(o[mt][nt], A0[mt][0], A0[mt][1], A0[mt][2], A0[mt][3], B00, B01);
                }
            }
        }
    }

    __syncthreads();

    // ---- epilogue: normalize by 1/l and store ----
    {
        float il[8];
#pragma unroll
        for (int j = 0; j < 8; j++) il[j] = 1.0f / fL[g + 8 * j];
        float* ob = out + ((size_t)b * SEQ + q0) * DIM;
#pragma unroll
        for (int mt = 0; mt < 4; mt++) {
            float ilo = il[2 * mt], ihi = il[2 * mt + 1];
            int r = mt * 16 + g;
#pragma unroll
            for (int nt = 0; nt < 4; nt++) {
                int c = nb + nt * 8 + (t << 1);
                float2 v0 = make_float2(o[mt][nt].x * ilo, o[mt][nt].y * ilo);
                float2 v1 = make_float2(o[mt][nt].z * ihi, o[mt][nt].w * ihi);
                *(float2*)(ob + r * DIM + c)       = v0;
                *(float2*)(ob + (r + 8) * DIM + c) = v1;
            }
        }
    }
}

extern "C" void kernel_launch(void* const* d_in, const int* in_sizes, int n_in,
                              void* d_out, int out_size) {
    const float* enc = (const float*)d_in[0];   // enc_outputs [8,2048,512]
    const float* dec = (const float*)d_in[1];   // dec_outputs [8,2048,512]
    float* out = (float*)d_out;                 // [8,2048,512]

    cudaFuncSetAttribute(attn_flash_v6,
                         cudaFuncAttributeMaxDynamicSharedMemorySize, SMEM_BYTES);

    dim3 grid(8 * (SEQ / QT));   // 256 CTAs
    attn_flash_v6<<<grid, NT_, SMEM_BYTES>>>(enc, dec, out);
}

// round 7
// speedup vs baseline: 1.0457x; 1.0191x over previous
#include <cuda_runtime.h>
#include <cuda_bf16.h>
#include <cstdint>

#define SEQ 2048
#define DIM 512
#define QT  32
#define KT  16
#define NT_ 256

#define QS32 260   // word stride of Q/K bf16-pair rows (260 % 32 == 4)
#define SPST 20    // float stride of partial-score rows (16 cols + 4 pad)
#define PS   12    // word stride of P pair rows (8 pairs + 4 pad)

// smem word offsets (total 28,384 words = 113,536 B per CTA -> 2 CTAs/SM)
#define W_Q0 0
#define W_Q1 8320
#define W_K0 16640
#define W_K1 20800
#define W_SP 24960          // 4 buffers x (32*20 = 640)
#define W_P0 27520
#define W_P1 27904
#define W_M  28288
#define W_L  28320
#define W_SC 28352
#define SMEM_WORDS 28384
#define SMEM_BYTES (SMEM_WORDS * 4)

__device__ __forceinline__ uint32_t smem_u32(const void* p) {
    uint32_t a;
    asm("{ .reg .u64 t; cvta.to.shared.u64 t, %1; cvt.u32.u64 %0, t; }" : "=r"(a) : "l"(p));
    return a;
}

// split fp32 pair (x=even-k, y=odd-k) into bf16 hi pair + bf16 residual pair
__device__ __forceinline__ void cvt2(float x, float y, uint32_t& hip, uint32_t& lop) {
    __nv_bfloat16 bx = __float2bfloat16_rn(x);
    __nv_bfloat16 by = __float2bfloat16_rn(y);
    float rx = x - __bfloat162float(bx);
    float ry = y - __bfloat162float(by);
    __nv_bfloat162 h; h.x = bx; h.y = by;
    __nv_bfloat162 l; l.x = __float2bfloat16_rn(rx); l.y = __float2bfloat16_rn(ry);
    hip = *reinterpret_cast<uint32_t*>(&h);
    lop = *reinterpret_cast<uint32_t*>(&l);
}

__device__ __forceinline__ void mma16(float4& d,
                                      uint32_t a0, uint32_t a1, uint32_t a2, uint32_t a3,
                                      uint32_t b0, uint32_t b1) {
    asm volatile(
        "mma.sync.aligned.m16n8k16.row.col.f32.bf16.bf16.f32 "
        "{%0,%1,%2,%3},{%4,%5,%6,%7},{%8,%9},{%0,%1,%2,%3};"
        : "+f"(d.x), "+f"(d.y), "+f"(d.z), "+f"(d.w)
        : "r"(a0), "r"(a1), "r"(a2), "r"(a3), "r"(b0), "r"(b1));
}

__device__ __forceinline__ void ldsm4(uint32_t& r0, uint32_t& r1, uint32_t& r2, uint32_t& r3,
                                      uint32_t a) {
    asm volatile("ldmatrix.sync.aligned.m8n8.x4.shared.b16 {%0,%1,%2,%3}, [%4];"
                 : "=r"(r0), "=r"(r1), "=r"(r2), "=r"(r3) : "r"(a));
}
__device__ __forceinline__ void ldsm4t(uint32_t& r0, uint32_t& r1, uint32_t& r2, uint32_t& r3,
                                       uint32_t a) {
    asm volatile("ldmatrix.sync.aligned.m8n8.x4.trans.shared.b16 {%0,%1,%2,%3}, [%4];"
                 : "=r"(r0), "=r"(r1), "=r"(r2), "=r"(r3) : "r"(a));
}

__global__ void __launch_bounds__(NT_, 2)
attn_flash_v7(const float* __restrict__ enc,
              const float* __restrict__ dec,
              float* __restrict__ out) {
    extern __shared__ uint32_t sm[];
    float* fM  = (float*)(sm + W_M);
    float* fL  = (float*)(sm + W_L);
    float* fSc = (float*)(sm + W_SC);

    const uint32_t sb = smem_u32(sm);
    const int tid  = threadIdx.x;
    const int lane = tid & 31;
    const int wid  = tid >> 5;           // 0..7
    const int g = lane >> 2;
    const int t = lane & 3;
    const int l16 = lane & 15;
    const int lhi = lane >> 4;

    const int b  = blockIdx.x >> 6;           // 64 q-tiles per batch
    const int q0 = (blockIdx.x & 63) * QT;
    const float* decb = dec + ((size_t)b * SEQ + q0) * DIM;
    const float* encb = enc + (size_t)b * SEQ * DIM;

    // ---- load Q tile, split to bf16 hi/lo ----
#pragma unroll
    for (int j = 0; j < 16; j++) {
        int i  = tid + j * NT_;              // 4096 float4
        int r  = i >> 7;
        int c4 = (i & 127) << 2;
        float4 v = *(const float4*)(decb + r * DIM + c4);
        uint32_t h0, l0, h1, l1;
        cvt2(v.x, v.y, h0, l0);
        cvt2(v.z, v.w, h1, l1);
        uint32_t w = r * QS32 + (c4 >> 1);
        *(uint2*)(sm + W_Q0 + w) = make_uint2(h0, h1);
        *(uint2*)(sm + W_Q1 + w) = make_uint2(l0, l1);
    }
    if (tid < QT) { fM[tid] = -1e30f; fL[tid] = 0.0f; }

    // GEMM1 roles: 2m x 1n x 4k  (warp tile 16x16, k-slice 128)
    const int wm = wid >> 2;     // 0..1
    const int wk = wid & 3;      // 0..3
    const int nb = wid * 64;     // GEMM2 column slice (64 wide)

    // ---- prefetch rows 0..3 of K[0] ----
    float4 kreg[2];
#pragma unroll
    for (int j = 0; j < 2; j++) {
        int i = tid + j * NT_;
        int r = i >> 7, c4 = (i & 127) << 2;
        kreg[j] = *(const float4*)(encb + (size_t)r * DIM + c4);
    }

    // ldmatrix byte-address bases
    uint32_t aQ0 = sb + 4u * (W_Q0 + (wm * 16 + l16) * QS32) + wk * 256 + lhi * 16;
    uint32_t aQ1 = aQ0 + 4u * (W_Q1 - W_Q0);
    const int mi = lane >> 3;
    const int bn = (mi >> 1) * 8 + (lane & 7);
    uint32_t aBh = sb + 4u * (W_K0 + bn * QS32) + wk * 256 + (mi & 1) * 16;
    uint32_t aBl = aBh + 4u * (W_K1 - W_K0);
    uint32_t aP0 = sb + 4u * (W_P0 + l16 * PS) + lhi * 16;
    uint32_t aP1 = aP0 + 4u * (W_P1 - W_P0);
    uint32_t aE0 = sb + 4u * (W_K0 + l16 * QS32) + nb * 2 + lhi * 16;
    uint32_t aE1 = aE0 + 4u * (W_K1 - W_K0);

    float4 o[2][8];
#pragma unroll
    for (int mt = 0; mt < 2; mt++)
#pragma unroll
        for (int nt = 0; nt < 8; nt++) o[mt][nt] = make_float4(0.f, 0.f, 0.f, 0.f);

    for (int kt = 0; kt < SEQ / KT; kt++) {
        __syncthreads();   // prior GEMM2 done with K/P; Sp free

        // ---- direct-load rows 4..15 of current K, store whole tile split ----
        const float* kg = encb + (size_t)kt * KT * DIM;
        float4 dk[6];
#pragma unroll
        for (int jj = 0; jj < 6; jj++) {
            int i = tid + (jj + 2) * NT_;
            int r = i >> 7, c4 = (i & 127) << 2;
            dk[jj] = *(const float4*)(kg + (size_t)r * DIM + c4);
        }
#pragma unroll
        for (int j = 0; j < 2; j++) {
            int i = tid + j * NT_;
            int r = i >> 7, c4 = (i & 127) << 2;
            uint32_t h0, l0, h1, l1;
            cvt2(kreg[j].x, kreg[j].y, h0, l0);
            cvt2(kreg[j].z, kreg[j].w, h1, l1);
            uint32_t w = r * QS32 + (c4 >> 1);
            *(uint2*)(sm + W_K0 + w) = make_uint2(h0, h1);
            *(uint2*)(sm + W_K1 + w) = make_uint2(l0, l1);
        }
#pragma unroll
        for (int jj = 0; jj < 6; jj++) {
            int i = tid + (jj + 2) * NT_;
            int r = i >> 7, c4 = (i & 127) << 2;
            uint32_t h0, l0, h1, l1;
            cvt2(dk[jj].x, dk[jj].y, h0, l0);
            cvt2(dk[jj].z, dk[jj].w, h1, l1);
            uint32_t w = r * QS32 + (c4 >> 1);
            *(uint2*)(sm + W_K0 + w) = make_uint2(h0, h1);
            *(uint2*)(sm + W_K1 + w) = make_uint2(l0, l1);
        }
        // ---- prefetch rows 0..3 of next K tile ----
        if (kt + 1 < SEQ / KT) {
            const float* kg2 = encb + (size_t)(kt + 1) * KT * DIM;
#pragma unroll
            for (int j = 0; j < 2; j++) {
                int i = tid + j * NT_;
                int r = i >> 7, c4 = (i & 127) << 2;
                kreg[j] = *(const float4*)(kg2 + (size_t)r * DIM + c4);
            }
        }
        __syncthreads();

        // ---- GEMM1 (4-way split-k): S-partial[16x16] per warp ----
        {
            float4 ch0 = make_float4(0.f, 0.f, 0.f, 0.f);
            float4 ch1 = ch0, cm0 = ch0, cm1 = ch0, cl0 = ch0, cl1 = ch0;
#pragma unroll
            for (int s = 0; s < 8; s++) {
                uint32_t a0, a1, a2, a3, r0, r1, r2, r3;
                ldsm4(a0, a1, a2, a3, aQ0 + s * 32);
                ldsm4(r0, r1, r2, r3, aQ1 + s * 32);
                uint32_t bh0, bh1, bh2, bh3, bl0, bl1, bl2, bl3;
                ldsm4(bh0, bh1, bh2, bh3, aBh + s * 32);
                ldsm4(bl0, bl1, bl2, bl3, aBl + s * 32);
                mma16(ch0, a0, a1, a2, a3, bh0, bh1);   // nt0 hi*hi
                mma16(ch1, a0, a1, a2, a3, bh2, bh3);   // nt1 hi*hi
                mma16(cm0, a0, a1, a2, a3, bl0, bl1);   // nt0 hi*lo
                mma16(cm1, a0, a1, a2, a3, bl2, bl3);   // nt1 hi*lo
                mma16(cl0, r0, r1, r2, r3, bh0, bh1);   // nt0 lo*hi
                mma16(cl1, r0, r1, r2, r3, bh2, bh3);   // nt1 lo*hi
            }
            float4 u, v;
            u.x = ch0.x + cm0.x + cl0.x; u.y = ch0.y + cm0.y + cl0.y;
            u.z = ch0.z + cm0.z + cl0.z; u.w = ch0.w + cm0.w + cl0.w;
            v.x = ch1.x + cm1.x + cl1.x; v.y = ch1.y + cm1.y + cl1.y;
            v.z = ch1.z + cm1.z + cl1.z; v.w = ch1.w + cm1.w + cl1.w;
            float* sp = (float*)(sm + W_SP + wk * 640);
            int rr = wm * 16 + g;
            int cc = t << 1;
            *(float2*)(sp + rr * SPST + cc)           = make_float2(u.x, u.y);
            *(float2*)(sp + (rr + 8) * SPST + cc)     = make_float2(u.z, u.w);
            *(float2*)(sp + rr * SPST + cc + 8)       = make_float2(v.x, v.y);
            *(float2*)(sp + (rr + 8) * SPST + cc + 8) = make_float2(v.z, v.w);
        }
        __syncthreads();

        // ---- online softmax: 8 warps x 4 rows, 8 lanes/row, sum 4 k-partials ----
        {
            int row = (wid << 2) + (lane >> 3);
            int c2  = (lane & 7) << 1;
            const float* spb = (const float*)(sm + W_SP) + row * SPST + c2;
            float2 q0_ = *(const float2*)(spb);
            float2 q1_ = *(const float2*)(spb + 640);
            float2 q2_ = *(const float2*)(spb + 1280);
            float2 q3_ = *(const float2*)(spb + 1920);
            float s0 = (q0_.x + q1_.x) + (q2_.x + q3_.x);
            float s1 = (q0_.y + q1_.y) + (q2_.y + q3_.y);
            float mx = fmaxf(s0, s1);
            mx = fmaxf(mx, __shfl_xor_sync(0xffffffffu, mx, 1));
            mx = fmaxf(mx, __shfl_xor_sync(0xffffffffu, mx, 2));
            mx = fmaxf(mx, __shfl_xor_sync(0xffffffffu, mx, 4));
            float mo = fM[row];
            float mn = fmaxf(mo, mx);
            float p0 = __expf(s0 - mn), p1 = __expf(s1 - mn);
            float su = p0 + p1;
            su += __shfl_xor_sync(0xffffffffu, su, 1);
            su += __shfl_xor_sync(0xffffffffu, su, 2);
            su += __shfl_xor_sync(0xffffffffu, su, 4);
            if ((lane & 7) == 0) {
                float sc = __expf(mo - mn);
                fSc[row] = sc;
                fM[row]  = mn;
                fL[row]  = fL[row] * sc + su;
            }
            uint32_t h, l;
            cvt2(p0, p1, h, l);
            sm[W_P0 + row * PS + (lane & 7)] = h;
            sm[W_P1 + row * PS + (lane & 7)] = l;
        }
        __syncthreads();

        // ---- rescale O ----
        {
            float sc[4];
#pragma unroll
            for (int j = 0; j < 4; j++) sc[j] = fSc[g + 8 * j];
#pragma unroll
            for (int mt = 0; mt < 2; mt++) {
                float slo = sc[2 * mt], shi = sc[2 * mt + 1];
#pragma unroll
                for (int nt = 0; nt < 8; nt++) {
                    o[mt][nt].x *= slo; o[mt][nt].y *= slo;
                    o[mt][nt].z *= shi; o[mt][nt].w *= shi;
                }
            }
        }

        // ---- GEMM2: O[32 x 64/warp] += P[32x16] @ E[16x512] ----
        {
            uint32_t A0[2][4], A1[2][4];
#pragma unroll
            for (int mt = 0; mt < 2; mt++) {
                uint32_t off = (uint32_t)(mt * 16 * PS) * 4;
                ldsm4(A0[mt][0], A0[mt][1], A0[mt][2], A0[mt][3], aP0 + off);
                ldsm4(A1[mt][0], A1[mt][1], A1[mt][2], A1[mt][3], aP1 + off);
            }
#pragma unroll
            for (int ntp = 0; ntp < 4; ntp++) {
                uint32_t bh0, bh1, bh2, bh3, bl0, bl1, bl2, bl3;
                ldsm4t(bh0, bh1, bh2, bh3, aE0 + ntp * 32);
                ldsm4t(bl0, bl1, bl2, bl3, aE1 + ntp * 32);
                int n0 = ntp * 2, n1 = ntp * 2 + 1;
#pragma unroll
                for (int mt = 0; mt < 2; mt++) {
                    mma16(o[mt][n0], A0[mt][0], A0[mt][1], A0[mt][2], A0[mt][3], bl0, bl1);
                    mma16(o[mt][n0], A1[mt][0], A1[mt][1], A1[mt][2], A1[mt][3], bh0, bh1);
                    mma16(o[mt][n0], A0[mt][0], A0[mt][1], A0[mt][2], A0[mt][3], bh0, bh1);
                    mma16(o[mt][n1], A0[mt][0], A0[mt][1], A0[mt][2], A0[mt][3], bl2, bl3);
                    mma16(o[mt][n1], A1[mt][0], A1[mt][1], A1[mt][2], A1[mt][3], bh2, bh3);
                    mma16(o[mt][n1], A0[mt][0], A0[mt][1], A0[mt][2], A0[mt][3], bh2, bh3);
                }
            }
        }
    }

    __syncthreads();

    // ---- epilogue: normalize by 1/l and store ----
    {
        float il[4];
#pragma unroll
        for (int j = 0; j < 4; j++) il[j] = 1.0f / fL[g + 8 * j];
        float* ob = out + ((size_t)b * SEQ + q0) * DIM;
#pragma unroll
        for (int mt = 0; mt < 2; mt++) {
            float ilo = il[2 * mt], ihi = il[2 * mt + 1];
            int r = mt * 16 + g;
#pragma unroll
            for (int nt = 0; nt < 8; nt++) {
                int c = nb + nt * 8 + (t << 1);
                float2 v0 = make_float2(o[mt][nt].x * ilo, o[mt][nt].y * ilo);
                float2 v1 = make_float2(o[mt][nt].z * ihi, o[mt][nt].w * ihi);
                *(float2*)(ob + r * DIM + c)       = v0;
                *(float2*)(ob + (r + 8) * DIM + c) = v1;
            }
        }
    }
}

extern "C" void kernel_launch(void* const* d_in, const int* in_sizes, int n_in,
                              void* d_out, int out_size) {
    const float* enc = (const float*)d_in[0];   // enc_outputs [8,2048,512]
    const float* dec = (const float*)d_in[1];   // dec_outputs [8,2048,512]
    float* out = (float*)d_out;                 // [8,2048,512]

    cudaFuncSetAttribute(attn_flash_v7,
                         cudaFuncAttributeMaxDynamicSharedMemorySize, SMEM_BYTES);

    dim3 grid(8 * (SEQ / QT));   // 512 CTAs, 2 per SM
    attn_flash_v7<<<grid, NT_, SMEM_BYTES>>>(enc, dec, out);
}

// round 8
// speedup vs baseline: 1.1405x; 1.0906x over previous
#include <cuda_runtime.h>
#include <cuda_bf16.h>
#include <cstdint>

#define SEQ 2048
#define DIM 512
#define QT  32
#define KT  32
#define NT_ 256

#define QS32 260      // word stride of K bf16-pair rows (260 % 32 == 4)
#define KBW  8320     // words per K half-tile (32 rows x 260)
#define SPST 36       // float stride of partial-score rows
#define PS   20       // word stride of P pair rows (16 pairs + 4 pad)

// smem word offsets: two K buffers (hi+lo each), Sp, P, stats
#define W_B0H 0
#define W_B0L 8320
#define W_B1H 16640
#define W_B1L 24960
#define W_SP  33280   // 4 buffers x 32x36 = 4x1152
#define W_P0  37888
#define W_P1  38528
#define W_M   39168
#define W_L   39200
#define W_SC  39232
#define SMEM_WORDS 39264
#define SMEM_BYTES (SMEM_WORDS * 4)   // 157,056 B -> 1 CTA/SM

__device__ __forceinline__ uint32_t smem_u32(const void* p) {
    uint32_t a;
    asm("{ .reg .u64 t; cvta.to.shared.u64 t, %1; cvt.u32.u64 %0, t; }" : "=r"(a) : "l"(p));
    return a;
}

// split fp32 pair (x=even-k, y=odd-k) into bf16 hi pair + bf16 residual pair
__device__ __forceinline__ void cvt2(float x, float y, uint32_t& hip, uint32_t& lop) {
    __nv_bfloat16 bx = __float2bfloat16_rn(x);
    __nv_bfloat16 by = __float2bfloat16_rn(y);
    float rx = x - __bfloat162float(bx);
    float ry = y - __bfloat162float(by);
    __nv_bfloat162 h; h.x = bx; h.y = by;
    __nv_bfloat162 l; l.x = __float2bfloat16_rn(rx); l.y = __float2bfloat16_rn(ry);
    hip = *reinterpret_cast<uint32_t*>(&h);
    lop = *reinterpret_cast<uint32_t*>(&l);
}

__device__ __forceinline__ void mma16(float4& d,
                                      uint32_t a0, uint32_t a1, uint32_t a2, uint32_t a3,
                                      uint32_t b0, uint32_t b1) {
    asm volatile(
        "mma.sync.aligned.m16n8k16.row.col.f32.bf16.bf16.f32 "
        "{%0,%1,%2,%3},{%4,%5,%6,%7},{%8,%9},{%0,%1,%2,%3};"
        : "+f"(d.x), "+f"(d.y), "+f"(d.z), "+f"(d.w)
        : "r"(a0), "r"(a1), "r"(a2), "r"(a3), "r"(b0), "r"(b1));
}

__device__ __forceinline__ void ldsm4(uint32_t& r0, uint32_t& r1, uint32_t& r2, uint32_t& r3,
                                      uint32_t a) {
    asm volatile("ldmatrix.sync.aligned.m8n8.x4.shared.b16 {%0,%1,%2,%3}, [%4];"
                 : "=r"(r0), "=r"(r1), "=r"(r2), "=r"(r3) : "r"(a));
}
__device__ __forceinline__ void ldsm4t(uint32_t& r0, uint32_t& r1, uint32_t& r2, uint32_t& r3,
                                       uint32_t a) {
    asm volatile("ldmatrix.sync.aligned.m8n8.x4.trans.shared.b16 {%0,%1,%2,%3}, [%4];"
                 : "=r"(r0), "=r"(r1), "=r"(r2), "=r"(r3) : "r"(a));
}

__global__ void __launch_bounds__(NT_, 1)
attn_flash_v8(const float* __restrict__ enc,
              const float* __restrict__ dec,
              float* __restrict__ out) {
    extern __shared__ uint32_t sm[];
    float* fM  = (float*)(sm + W_M);
    float* fL  = (float*)(sm + W_L);
    float* fSc = (float*)(sm + W_SC);

    const uint32_t sb = smem_u32(sm);
    const int tid  = threadIdx.x;
    const int lane = tid & 31;
    const int wid  = tid >> 5;           // 0..7
    const int g  = lane >> 2;
    const int t  = lane & 3;
    const int l16 = lane & 15;
    const int lhi = lane >> 4;
    const int l8  = lane & 7;
    const int mi  = lane >> 3;

    const int b  = blockIdx.x >> 6;           // 64 q-tiles per batch
    const int q0 = (blockIdx.x & 63) * QT;
    const float* decb = dec + ((size_t)b * SEQ + q0) * DIM;
    const float* encb = enc + (size_t)b * SEQ * DIM;

    const int wm = wid >> 2;     // GEMM1 m-half 0..1
    const int wk = wid & 3;      // GEMM1 k-slice 0..3 (128 each)
    const int nb = wid * 64;     // GEMM2 column slice (64 wide)

    // ---- prologue: stage Q (split) into buf1, init stats ----
#pragma unroll
    for (int j = 0; j < 16; j++) {
        int i  = tid + j * NT_;              // 4096 float4
        int r  = i >> 7;
        int c4 = (i & 127) << 2;
        float4 v = *(const float4*)(decb + r * DIM + c4);
        uint32_t h0, l0, h1, l1;
        cvt2(v.x, v.y, h0, l0);
        cvt2(v.z, v.w, h1, l1);
        uint32_t w = r * QS32 + (c4 >> 1);
        *(uint2*)(sm + W_B1H + w) = make_uint2(h0, h1);
        *(uint2*)(sm + W_B1L + w) = make_uint2(l0, l1);
    }
    if (tid < QT) { fM[tid] = -1e30f; fL[tid] = 0.0f; }
    __syncthreads();

    // ---- extract Q fragments into registers (64 regs) ----
    uint32_t qh[8][4], ql[8][4];
    {
        uint32_t aQh = sb + 4u * (W_B1H + (wm * 16 + l16) * QS32) + wk * 256 + lhi * 16;
        uint32_t aQl = aQh + 4u * KBW;
#pragma unroll
        for (int s = 0; s < 8; s++) {
            ldsm4(qh[s][0], qh[s][1], qh[s][2], qh[s][3], aQh + s * 32);
            ldsm4(ql[s][0], ql[s][1], ql[s][2], ql[s][3], aQl + s * 32);
        }
    }

    // ---- load K tile 0 into buf0 ----
#pragma unroll
    for (int j = 0; j < 16; j++) {
        int i  = tid + j * NT_;
        int r  = i >> 7;
        int c4 = (i & 127) << 2;
        float4 v = *(const float4*)(encb + (size_t)r * DIM + c4);
        uint32_t h0, l0, h1, l1;
        cvt2(v.x, v.y, h0, l0);
        cvt2(v.z, v.w, h1, l1);
        uint32_t w = r * QS32 + (c4 >> 1);
        *(uint2*)(sm + W_B0H + w) = make_uint2(h0, h1);
        *(uint2*)(sm + W_B0L + w) = make_uint2(l0, l1);
    }

    float4 o[2][8];
#pragma unroll
    for (int mt = 0; mt < 2; mt++)
#pragma unroll
        for (int nt = 0; nt < 8; nt++) o[mt][nt] = make_float4(0.f, 0.f, 0.f, 0.f);

    for (int it = 0; it < SEQ / KT; it++) {
        __syncthreads();   // buf(it) visible; buf(it^1) free (GEMM2 of it-1 done)

        const uint32_t kb = sb + ((it & 1) ? (uint32_t)(W_B1H * 4) : 0u);
        uint32_t* kd = sm + ((it & 1) ? W_B0H : W_B1H);
        const float* kgn = encb + (size_t)(it + 1) * KT * DIM;
        const bool more = (it + 1 < SEQ / KT);

        // LDG half A (rows 0..15) of next K — latency hides under GEMM1
        float4 ka[8];
        if (more) {
#pragma unroll
            for (int j = 0; j < 8; j++) {
                int i = tid + j * NT_;
                int r = i >> 7, c4 = (i & 127) << 2;
                ka[j] = *(const float4*)(kgn + (size_t)r * DIM + c4);
            }
        }

        // ---- GEMM1: S-partial[16x32] per warp over its k128 slice ----
        {
            uint32_t aBhA = kb + 4u * (((mi >> 1) * 8 + l8) * QS32) + wk * 256 + (mi & 1) * 16;
            uint32_t aBhB = aBhA + 16u * QS32 * 4;
            uint32_t aBlA = aBhA + 4u * KBW;
            uint32_t aBlB = aBhB + 4u * KBW;
            float4 cH[4], cX[4];
#pragma unroll
            for (int j = 0; j < 4; j++) {
                cH[j] = make_float4(0.f, 0.f, 0.f, 0.f);
                cX[j] = make_float4(0.f, 0.f, 0.f, 0.f);
            }
#pragma unroll
            for (int s = 0; s < 8; s++) {
                uint32_t bh0, bh1, bh2, bh3, bh4, bh5, bh6, bh7;
                uint32_t bl0, bl1, bl2, bl3, bl4, bl5, bl6, bl7;
                ldsm4(bh0, bh1, bh2, bh3, aBhA + s * 32);
                ldsm4(bh4, bh5, bh6, bh7, aBhB + s * 32);
                ldsm4(bl0, bl1, bl2, bl3, aBlA + s * 32);
                ldsm4(bl4, bl5, bl6, bl7, aBlB + s * 32);
                mma16(cH[0], qh[s][0], qh[s][1], qh[s][2], qh[s][3], bh0, bh1);
                mma16(cH[1], qh[s][0], qh[s][1], qh[s][2], qh[s][3], bh2, bh3);
                mma16(cH[2], qh[s][0], qh[s][1], qh[s][2], qh[s][3], bh4, bh5);
                mma16(cH[3], qh[s][0], qh[s][1], qh[s][2], qh[s][3], bh6, bh7);
                mma16(cX[0], qh[s][0], qh[s][1], qh[s][2], qh[s][3], bl0, bl1);
                mma16(cX[1], qh[s][0], qh[s][1], qh[s][2], qh[s][3], bl2, bl3);
                mma16(cX[2], qh[s][0], qh[s][1], qh[s][2], qh[s][3], bl4, bl5);
                mma16(cX[3], qh[s][0], qh[s][1], qh[s][2], qh[s][3], bl6, bl7);
                mma16(cX[0], ql[s][0], ql[s][1], ql[s][2], ql[s][3], bh0, bh1);
                mma16(cX[1], ql[s][0], ql[s][1], ql[s][2], ql[s][3], bh2, bh3);
                mma16(cX[2], ql[s][0], ql[s][1], ql[s][2], ql[s][3], bh4, bh5);
                mma16(cX[3], ql[s][0], ql[s][1], ql[s][2], ql[s][3], bh6, bh7);
            }
            float* sp = (float*)(sm + W_SP + wk * 1152);
            int rr = wm * 16 + g;
#pragma unroll
            for (int j = 0; j < 4; j++) {
                int cc = j * 8 + (t << 1);
                *(float2*)(sp + rr * SPST + cc) =
                    make_float2(cH[j].x + cX[j].x, cH[j].y + cX[j].y);
                *(float2*)(sp + (rr + 8) * SPST + cc) =
                    make_float2(cH[j].z + cX[j].z, cH[j].w + cX[j].w);
            }
        }

        // ---- store half A of next K into the spare buffer ----
        if (more) {
#pragma unroll
            for (int j = 0; j < 8; j++) {
                int i = tid + j * NT_;
                int r = i >> 7, c4 = (i & 127) << 2;
                uint32_t h0, l0, h1, l1;
                cvt2(ka[j].x, ka[j].y, h0, l0);
                cvt2(ka[j].z, ka[j].w, h1, l1);
                uint32_t w = r * QS32 + (c4 >> 1);
                *(uint2*)(kd + w) = make_uint2(h0, h1);
                *(uint2*)(kd + KBW + w) = make_uint2(l0, l1);
            }
        }
        __syncthreads();

        // ---- softmax (+ LDG/STS half B of next K, hidden under it) ----
        {
            float4 kb2[2][2];   // 4 float4 unrolled as scalars to limit pressure
            float4 kb3[4];
            if (more) {
#pragma unroll
                for (int j = 0; j < 4; j++) {
                    int i = tid + (j + 8) * NT_;
                    int r = i >> 7, c4 = (i & 127) << 2;
                    kb2[j >> 1][j & 1] = *(const float4*)(kgn + (size_t)r * DIM + c4);
                }
#pragma unroll
                for (int j = 0; j < 4; j++) {
                    int i = tid + (j + 12) * NT_;
                    int r = i >> 7, c4 = (i & 127) << 2;
                    kb3[j] = *(const float4*)(kgn + (size_t)r * DIM + c4);
                }
            }

            int row = tid >> 3;
            int c4s = (tid & 7) << 2;
            const float* spb = (const float*)(sm + W_SP) + row * SPST + c4s;
            float4 u0 = *(const float4*)(spb);
            float4 u1 = *(const float4*)(spb + 1152);
            float4 u2 = *(const float4*)(spb + 2304);
            float4 u3 = *(const float4*)(spb + 3456);
            float s0 = (u0.x + u1.x) + (u2.x + u3.x);
            float s1 = (u0.y + u1.y) + (u2.y + u3.y);
            float s2 = (u0.z + u1.z) + (u2.z + u3.z);
            float s3 = (u0.w + u1.w) + (u2.w + u3.w);
            float mx = fmaxf(fmaxf(s0, s1), fmaxf(s2, s3));
            mx = fmaxf(mx, __shfl_xor_sync(0xffffffffu, mx, 1));
            mx = fmaxf(mx, __shfl_xor_sync(0xffffffffu, mx, 2));
            mx = fmaxf(mx, __shfl_xor_sync(0xffffffffu, mx, 4));
            float mo = fM[row];
            float mn = fmaxf(mo, mx);
            float p0 = __expf(s0 - mn), p1 = __expf(s1 - mn);
            float p2 = __expf(s2 - mn), p3 = __expf(s3 - mn);
            float su = (p0 + p1) + (p2 + p3);
            su += __shfl_xor_sync(0xffffffffu, su, 1);
            su += __shfl_xor_sync(0xffffffffu, su, 2);
            su += __shfl_xor_sync(0xffffffffu, su, 4);
            if ((tid & 7) == 0) {
                float sc = __expf(mo - mn);
                fSc[row] = sc;
                fM[row]  = mn;
                fL[row]  = fL[row] * sc + su;
            }
            uint32_t h0, l0, h1, l1;
            cvt2(p0, p1, h0, l0);
            cvt2(p2, p3, h1, l1);
            uint32_t w = row * PS + ((tid & 7) << 1);
            *(uint2*)(sm + W_P0 + w) = make_uint2(h0, h1);
            *(uint2*)(sm + W_P1 + w) = make_uint2(l0, l1);

            if (more) {
#pragma unroll
                for (int j = 0; j < 4; j++) {
                    int i = tid + (j + 8) * NT_;
                    int r = i >> 7, c4 = (i & 127) << 2;
                    uint32_t hh0, ll0, hh1, ll1;
                    float4 v = kb2[j >> 1][j & 1];
                    cvt2(v.x, v.y, hh0, ll0);
                    cvt2(v.z, v.w, hh1, ll1);
                    uint32_t ww = r * QS32 + (c4 >> 1);
                    *(uint2*)(kd + ww) = make_uint2(hh0, hh1);
                    *(uint2*)(kd + KBW + ww) = make_uint2(ll0, ll1);
                }
#pragma unroll
                for (int j = 0; j < 4; j++) {
                    int i = tid + (j + 12) * NT_;
                    int r = i >> 7, c4 = (i & 127) << 2;
                    uint32_t hh0, ll0, hh1, ll1;
                    cvt2(kb3[j].x, kb3[j].y, hh0, ll0);
                    cvt2(kb3[j].z, kb3[j].w, hh1, ll1);
                    uint32_t ww = r * QS32 + (c4 >> 1);
                    *(uint2*)(kd + ww) = make_uint2(hh0, hh1);
                    *(uint2*)(kd + KBW + ww) = make_uint2(ll0, ll1);
                }
            }
        }
        __syncthreads();

        // ---- rescale O ----
        {
            float sc[4];
#pragma unroll
            for (int j = 0; j < 4; j++) sc[j] = fSc[g + 8 * j];
#pragma unroll
            for (int mt = 0; mt < 2; mt++) {
                float slo = sc[2 * mt], shi = sc[2 * mt + 1];
#pragma unroll
                for (int nt = 0; nt < 8; nt++) {
                    o[mt][nt].x *= slo; o[mt][nt].y *= slo;
                    o[mt][nt].z *= shi; o[mt][nt].w *= shi;
                }
            }
        }

        // ---- GEMM2: O[32 x 64/warp] += P[32x32] @ E[32x512] ----
        {
            uint32_t aP0 = sb + 4u * (W_P0 + l16 * PS) + lhi * 16;
            uint32_t aP1 = aP0 + 4u * (W_P1 - W_P0);
            uint32_t aE0 = kb + 4u * (l16 * QS32) + (uint32_t)nb * 2 + lhi * 16;
            uint32_t aE1 = aE0 + 4u * KBW;
#pragma unroll
            for (int ks = 0; ks < 2; ks++) {
                uint32_t A0[2][4], A1[2][4];
#pragma unroll
                for (int mt = 0; mt < 2; mt++) {
                    uint32_t off = (uint32_t)(mt * 16 * PS + ks * 8) * 4;
                    ldsm4(A0[mt][0], A0[mt][1], A0[mt][2], A0[mt][3], aP0 + off);
                    ldsm4(A1[mt][0], A1[mt][1], A1[mt][2], A1[mt][3], aP1 + off);
                }
                uint32_t eoff = (uint32_t)(ks * 16 * QS32) * 4;
#pragma unroll
                for (int ntp = 0; ntp < 4; ntp++) {
                    uint32_t bh0, bh1, bh2, bh3, bl0, bl1, bl2, bl3;
                    ldsm4t(bh0, bh1, bh2, bh3, aE0 + eoff + ntp * 32);
                    ldsm4t(bl0, bl1, bl2, bl3, aE1 + eoff + ntp * 32);
                    int n0 = ntp * 2, n1 = ntp * 2 + 1;
#pragma unroll
                    for (int mt = 0; mt < 2; mt++) {
                        mma16(o[mt][n0], A0[mt][0], A0[mt][1], A0[mt][2], A0[mt][3], bl0, bl1);
                        mma16(o[mt][n0], A1[mt][0], A1[mt][1], A1[mt][2], A1[mt][3], bh0, bh1);
                        mma16(o[mt][n0], A0[mt][0], A0[mt][1], A0[mt][2], A0[mt][3], bh0, bh1);
                        mma16(o[mt][n1], A0[mt][0], A0[mt][1], A0[mt][2], A0[mt][3], bl2, bl3);
                        mma16(o[mt][n1], A1[mt][0], A1[mt][1], A1[mt][2], A1[mt][3], bh2, bh3);
                        mma16(o[mt][n1], A0[mt][0], A0[mt][1], A0[mt][2], A0[mt][3], bh2, bh3);
                    }
                }
            }
        }
    }

    __syncthreads();

    // ---- epilogue: normalize by 1/l and store ----
    {
        float il[4];
#pragma unroll
        for (int j = 0; j < 4; j++) il[j] = 1.0f / fL[g + 8 * j];
        float* ob = out + ((size_t)b * SEQ + q0) * DIM;
#pragma unroll
        for (int mt = 0; mt < 2; mt++) {
            float ilo = il[2 * mt], ihi = il[2 * mt + 1];
            int r = mt * 16 + g;
#pragma unroll
            for (int nt = 0; nt < 8; nt++) {
                int c = nb + nt * 8 + (t << 1);
                float2 v0 = make_float2(o[mt][nt].x * ilo, o[mt][nt].y * ilo);
                float2 v1 = make_float2(o[mt][nt].z * ihi, o[mt][nt].w * ihi);
                *(float2*)(ob + r * DIM + c)       = v0;
                *(float2*)(ob + (r + 8) * DIM + c) = v1;
            }
        }
    }
}

extern "C" void kernel_launch(void* const* d_in, const int* in_sizes, int n_in,
                              void* d_out, int out_size) {
    const float* enc = (const float*)d_in[0];   // enc_outputs [8,2048,512]
    const float* dec = (const float*)d_in[1];   // dec_outputs [8,2048,512]
    float* out = (float*)d_out;                 // [8,2048,512]

    cudaFuncSetAttribute(attn_flash_v8,
                         cudaFuncAttributeMaxDynamicSharedMemorySize, SMEM_BYTES);

    dim3 grid(8 * (SEQ / QT));   // 512 CTAs, 1 per SM
    attn_flash_v8<<<grid, NT_, SMEM_BYTES>>>(enc, dec, out);
}